// round 16
// baseline (speedup 1.0000x reference)
#include <cuda_runtime.h>
#include <cuda_bf16.h>
#include <math.h>
#include <stdint.h>

#define N_NODES 20000
#define N_EDGES 640000
#define RTOT    40000     // both graphs merged
#define FIN     256
#define HDIM    512
#define MOUT    512
#define KTOP    1000

// ---------------- scratch (device globals; no allocation allowed) ----------
__device__ float g_x[(size_t)RTOT * HDIM];
__device__ __nv_bfloat16 g_ahi[(size_t)RTOT * HDIM];
__device__ __nv_bfloat16 g_alo[(size_t)RTOT * HDIM];
__device__ __nv_bfloat16 g_thi[(size_t)RTOT * HDIM];
__device__ __nv_bfloat16 g_tlo[(size_t)RTOT * HDIM];
#define WTOT (512*256 + 5*512*512)
__device__ __nv_bfloat16 g_whi[WTOT];
__device__ __nv_bfloat16 g_wlo[WTOT];
__device__ float g_o1[N_NODES * 2];
__device__ float g_o2[N_NODES * 2];
__device__ float g_dist[N_NODES];
__device__ int   g_deg[2 * N_NODES];
__device__ int   g_rowptr[2 * (N_NODES + 1)];
__device__ int   g_cursor[2 * (N_NODES + 1)];
__device__ int   g_csrsrc[2 * N_EDGES];

// ---------------- helpers ----------------------------------------------------
__device__ __forceinline__ uint32_t smem_u32(const void* p) {
    uint32_t a;
    asm("{ .reg .u64 t; cvta.to.shared.u64 t, %1; cvt.u32.u64 %0, t; }" : "=r"(a) : "l"(p));
    return a;
}
__device__ __forceinline__ __nv_bfloat162 bpack(__nv_bfloat16 a, __nv_bfloat16 b) {
    __nv_bfloat162 t; t.x = a; t.y = b; return t;
}
__device__ __forceinline__ void cp16(uint32_t dst, const void* src, int srcsize) {
    asm volatile("cp.async.cg.shared.global [%0], [%1], 16, %2;"
                 :: "r"(dst), "l"(src), "r"(srcsize) : "memory");
}
#define CP_COMMIT() asm volatile("cp.async.commit_group;" ::: "memory")
#define CP_WAIT1()  asm volatile("cp.async.wait_group 1;" ::: "memory")
#define CP_WAIT0()  asm volatile("cp.async.wait_group 0;" ::: "memory")
#define LDSM4(r0, r1, r2, r3, addr) \
    asm volatile("ldmatrix.sync.aligned.m8n8.x4.shared.b16 {%0,%1,%2,%3}, [%4];" \
                 : "=r"(r0), "=r"(r1), "=r"(r2), "=r"(r3) : "r"(addr))
#define LDSM2(r0, r1, addr) \
    asm volatile("ldmatrix.sync.aligned.m8n8.x2.shared.b16 {%0,%1}, [%2];" \
                 : "=r"(r0), "=r"(r1) : "r"(addr))
#define MMA16816(c, a, b) \
    asm volatile("mma.sync.aligned.m16n8k16.row.col.f32.bf16.bf16.f32 " \
                 "{%0,%1,%2,%3}, {%4,%5,%6,%7}, {%8,%9}, {%0,%1,%2,%3};" \
                 : "+f"((c)[0]), "+f"((c)[1]), "+f"((c)[2]), "+f"((c)[3]) \
                 : "r"((a)[0]), "r"((a)[1]), "r"((a)[2]), "r"((a)[3]), \
                   "r"((b)[0]), "r"((b)[1]))

// ---------------- CSR build (both graphs in one pass) ------------------------
__global__ __launch_bounds__(256) void zero_deg_kernel() {
    int i = blockIdx.x * blockDim.x + threadIdx.x;
    if (i < 2 * N_NODES) g_deg[i] = 0;
}
__global__ __launch_bounds__(256) void hist_kernel(const int* __restrict__ ei1,
                                                   const int* __restrict__ ei2) {
    int idx = blockIdx.x * blockDim.x + threadIdx.x;
    if (idx < 2 * N_EDGES) {
        int g = idx >= N_EDGES;
        int e = idx - g * N_EDGES;
        const int* dst = (g ? ei2 : ei1) + N_EDGES;
        atomicAdd(&g_deg[g * N_NODES + dst[e]], 1);
    }
}
__global__ __launch_bounds__(256) void scan_kernel() {
    __shared__ int sc[256];
    const int CH = 79;
    int gsel = blockIdx.x;
    const int* dg = g_deg + gsel * N_NODES;
    int* rp = g_rowptr + gsel * (N_NODES + 1);
    int* cu = g_cursor + gsel * (N_NODES + 1);
    int tid = threadIdx.x;
    int base = tid * CH;
    int ssum = 0;
    for (int i = 0; i < CH; i++) {
        int idx = base + i;
        if (idx < N_NODES) ssum += dg[idx];
    }
    sc[tid] = ssum;
    __syncthreads();
    for (int off = 1; off < 256; off <<= 1) {
        int v = 0;
        if (tid >= off) v = sc[tid - off];
        __syncthreads();
        sc[tid] += v;
        __syncthreads();
    }
    int off = (tid == 0) ? 0 : sc[tid - 1];
    for (int i = 0; i < CH; i++) {
        int idx = base + i;
        if (idx <= N_NODES) {
            rp[idx] = off;
            cu[idx] = off;
            if (idx < N_NODES) off += dg[idx];
        }
    }
}
__global__ __launch_bounds__(256) void fill_kernel(const int* __restrict__ ei1,
                                                   const int* __restrict__ ei2) {
    int idx = blockIdx.x * blockDim.x + threadIdx.x;
    if (idx < 2 * N_EDGES) {
        int g = idx >= N_EDGES;
        int e = idx - g * N_EDGES;
        const int* ei = g ? ei2 : ei1;
        int d = ei[N_EDGES + e];
        int p = atomicAdd(&g_cursor[g * (N_NODES + 1) + d], 1);
        g_csrsrc[g * N_EDGES + p] = ei[e];
    }
}

// ---------------- weight prep: transpose + bf16 split ------------------------
__global__ __launch_bounds__(256) void wprep_kernel(const float* __restrict__ src,
                                                    int K, int M,
                                                    __nv_bfloat16* __restrict__ dhi,
                                                    __nv_bfloat16* __restrict__ dlo) {
    int idx = blockIdx.x * blockDim.x + threadIdx.x;
    if (idx < K * M) {
        int k = idx / M, m = idx % M;
        float v = src[idx];
        __nv_bfloat16 h = __float2bfloat16(v);
        dhi[(size_t)m * K + k] = h;
        dlo[(size_t)m * K + k] = __float2bfloat16(v - __bfloat162float(h));
    }
}
// batched version for the five 512x512 weights (blockIdx.z selects)
__global__ __launch_bounds__(256) void wprep5_kernel(
    const float* __restrict__ w12, const float* __restrict__ w21,
    const float* __restrict__ w22, const float* __restrict__ w31,
    const float* __restrict__ w32,
    __nv_bfloat16* __restrict__ dhi, __nv_bfloat16* __restrict__ dlo) {
    int idx = blockIdx.x * blockDim.x + threadIdx.x;
    if (idx >= 512 * 512) return;
    const float* src;
    switch (blockIdx.z) {
        case 0: src = w12; break;
        case 1: src = w21; break;
        case 2: src = w22; break;
        case 3: src = w31; break;
        default: src = w32; break;
    }
    size_t off = (size_t)(512 * 256) + (size_t)blockIdx.z * 512 * 512;
    int k = idx / 512, m = idx % 512;
    float v = src[idx];
    __nv_bfloat16 h = __float2bfloat16(v);
    dhi[off + (size_t)m * 512 + k] = h;
    dlo[off + (size_t)m * 512 + k] = __float2bfloat16(v - __bfloat162float(h));
}

// ---------------- aggregation (emits hi/lo split) ----------------------------
__global__ __launch_bounds__(128) void agg256_kernel(const float* __restrict__ x1,
                                                     const float* __restrict__ x2) {
    int node = blockIdx.x;
    int g = node >= N_NODES;
    int ln = node - g * N_NODES;
    const float2* __restrict__ xv = (const float2*)(g ? x2 : x1);
    const int* __restrict__ rp = g_rowptr + g * (N_NODES + 1);
    const int* __restrict__ cs = g_csrsrc + g * N_EDGES;
    int tid = threadIdx.x;
    float2 acc = xv[(size_t)ln * 128 + tid];
    int s = rp[ln], e = rp[ln + 1];
#pragma unroll 4
    for (int i = s; i < e; i++) {
        int sr = cs[i];
        float2 r = xv[(size_t)sr * 128 + tid];
        acc.x += r.x; acc.y += r.y;
    }
    __nv_bfloat16 h0 = __float2bfloat16(acc.x), h1 = __float2bfloat16(acc.y);
    __nv_bfloat16 l0 = __float2bfloat16(acc.x - __bfloat162float(h0));
    __nv_bfloat16 l1 = __float2bfloat16(acc.y - __bfloat162float(h1));
    ((__nv_bfloat162*)(g_ahi + (size_t)node * FIN))[tid] = bpack(h0, h1);
    ((__nv_bfloat162*)(g_alo + (size_t)node * FIN))[tid] = bpack(l0, l1);
}

__global__ __launch_bounds__(128) void agg512_kernel() {
    int node = blockIdx.x;
    int g = node >= N_NODES;
    int ln = node - g * N_NODES;
    const float4* __restrict__ xv = (const float4*)g_x;
    const int* __restrict__ rp = g_rowptr + g * (N_NODES + 1);
    const int* __restrict__ cs = g_csrsrc + g * N_EDGES;
    int tid = threadIdx.x;
    int goff = g * N_NODES;
    float4 acc = xv[(size_t)node * 128 + tid];
    int s = rp[ln], e = rp[ln + 1];
#pragma unroll 4
    for (int i = s; i < e; i++) {
        int sr = cs[i] + goff;
        float4 r = xv[(size_t)sr * 128 + tid];
        acc.x += r.x; acc.y += r.y; acc.z += r.z; acc.w += r.w;
    }
    float f[4] = {acc.x, acc.y, acc.z, acc.w};
    __nv_bfloat16 h[4], l[4];
#pragma unroll
    for (int u = 0; u < 4; u++) {
        h[u] = __float2bfloat16(f[u]);
        l[u] = __float2bfloat16(f[u] - __bfloat162float(h[u]));
    }
    __nv_bfloat162* dh = (__nv_bfloat162*)(g_ahi + (size_t)node * HDIM + tid * 4);
    __nv_bfloat162* dl = (__nv_bfloat162*)(g_alo + (size_t)node * HDIM + tid * 4);
    dh[0] = bpack(h[0], h[1]); dh[1] = bpack(h[2], h[3]);
    dl[0] = bpack(l[0], l[1]); dl[1] = bpack(l[2], l[3]);
}

// ---------------- cp.async double-buffered mma.sync GEMM ---------------------
// C = relu(A[R,K] @ Wt^T + bias); A = (Ahi, Alo), B = Wt [MOUT,K] K-major.
// 3-product split. Tile BM=128, BN=64, BK=32; 8 warps (4x2), warp tile 32x32.
// Dynamic smem: 2 stages x (A_hi 10240 | A_lo 10240 | B_hi 5120 | B_lo 5120).
#define APAD 40
#define STG_BYTES 30720
#define OFF_ALO 10240
#define OFF_BHI 20480
#define OFF_BLO 25600
#define GEMM_SMEM (2 * STG_BYTES)

__device__ __forceinline__ void gemm_issue(
    uint32_t sb, int st,
    const __nv_bfloat16* __restrict__ Ahi, const __nv_bfloat16* __restrict__ Alo,
    const __nv_bfloat16* __restrict__ Bhi, const __nv_bfloat16* __restrict__ Blo,
    int rowBase, int colBase, int K, int c, int tid)
{
    uint32_t base = sb + st * STG_BYTES;
#pragma unroll
    for (int it = 0; it < 2; it++) {
        int idx = it * 256 + tid;             // 0..511
        int row = idx >> 2, seg = idx & 3;
        int ar = rowBase + row;
        int arc = ar < RTOT ? ar : 0;
        int ok = ar < RTOT ? 16 : 0;
        size_t so = (size_t)arc * K + c + seg * 8;
        uint32_t off = (uint32_t)(row * 80 + seg * 16);
        cp16(base + off, Ahi + so, ok);
        cp16(base + OFF_ALO + off, Alo + so, ok);
    }
    {
        int row = tid >> 2, seg = tid & 3;
        int br = colBase + row;               // always < MOUT
        size_t so = (size_t)br * K + c + seg * 8;
        uint32_t off = (uint32_t)(row * 80 + seg * 16);
        cp16(base + OFF_BHI + off, Bhi + so, 16);
        cp16(base + OFF_BLO + off, Blo + so, 16);
    }
}

__global__ __launch_bounds__(256) void mma_gemm_kernel(
    const __nv_bfloat16* __restrict__ Ahi, const __nv_bfloat16* __restrict__ Alo,
    const __nv_bfloat16* __restrict__ Bhi, const __nv_bfloat16* __restrict__ Blo,
    const float* __restrict__ bias,
    float* __restrict__ Cf,
    __nv_bfloat16* __restrict__ Chi, __nv_bfloat16* __restrict__ Clo,
    int K, int outSplit)
{
    extern __shared__ char gsm[];
    uint32_t sb = smem_u32(gsm);

    int tid = threadIdx.x, wid = tid >> 5, lane = tid & 31;
    int warpM = wid & 3;
    int warpN = wid >> 2;
    int rowBase = blockIdx.x * 128;
    int colBase = blockIdx.y * 64;

    float acc[2][4][4];
#pragma unroll
    for (int i = 0; i < 2; i++)
#pragma unroll
        for (int j = 0; j < 4; j++)
#pragma unroll
            for (int u = 0; u < 4; u++) acc[i][j][u] = 0.f;

    int nc = K >> 5;

    gemm_issue(sb, 0, Ahi, Alo, Bhi, Blo, rowBase, colBase, K, 0, tid);
    CP_COMMIT();

    for (int c = 0; c < nc; c++) {
        int st = c & 1;
        if (c + 1 < nc) {
            gemm_issue(sb, st ^ 1, Ahi, Alo, Bhi, Blo, rowBase, colBase, K, (c + 1) * 32, tid);
            CP_COMMIT();
            CP_WAIT1();
        } else {
            CP_WAIT0();
        }
        __syncthreads();

        uint32_t aHiB = sb + st * STG_BYTES;
        uint32_t aLoB = aHiB + OFF_ALO;
        uint32_t bHiB = aHiB + OFF_BHI;
        uint32_t bLoB = aHiB + OFF_BLO;
#pragma unroll
        for (int kk = 0; kk < 2; kk++) {
            int k0 = kk * 16;
            uint32_t ah[2][4], al[2][4], bh[4][2], bl[4][2];
#pragma unroll
            for (int i = 0; i < 2; i++) {
                uint32_t off = (uint32_t)((warpM * 32 + i * 16 + (lane & 15)) * APAD
                                          + k0 + (lane >> 4) * 8) * 2;
                LDSM4(ah[i][0], ah[i][1], ah[i][2], ah[i][3], aHiB + off);
                LDSM4(al[i][0], al[i][1], al[i][2], al[i][3], aLoB + off);
            }
#pragma unroll
            for (int j = 0; j < 4; j++) {
                int t = lane & 15;
                uint32_t off = (uint32_t)((warpN * 32 + j * 8 + (t & 7)) * APAD
                                          + k0 + (t >> 3) * 8) * 2;
                LDSM2(bh[j][0], bh[j][1], bHiB + off);
                LDSM2(bl[j][0], bl[j][1], bLoB + off);
            }
#pragma unroll
            for (int i = 0; i < 2; i++)
#pragma unroll
                for (int j = 0; j < 4; j++) {
                    MMA16816(acc[i][j], ah[i], bh[j]);
                    MMA16816(acc[i][j], al[i], bh[j]);
                    MMA16816(acc[i][j], ah[i], bl[j]);
                }
        }
        __syncthreads();
    }

    int quad = lane >> 2, qq = lane & 3;
#pragma unroll
    for (int i = 0; i < 2; i++) {
#pragma unroll
        for (int j = 0; j < 4; j++) {
            int col = colBase + warpN * 32 + j * 8 + qq * 2;
            float bv0 = __ldg(&bias[col]);
            float bv1 = __ldg(&bias[col + 1]);
#pragma unroll
            for (int h = 0; h < 2; h++) {
                int row = rowBase + warpM * 32 + i * 16 + quad + h * 8;
                if (row < RTOT) {
                    float v0 = fmaxf(acc[i][j][h * 2 + 0] + bv0, 0.f);
                    float v1 = fmaxf(acc[i][j][h * 2 + 1] + bv1, 0.f);
                    size_t o = (size_t)row * MOUT + col;
                    if (!outSplit) {
                        *(float2*)(Cf + o) = make_float2(v0, v1);
                    } else {
                        __nv_bfloat16 h0 = __float2bfloat16(v0);
                        __nv_bfloat16 h1 = __float2bfloat16(v1);
                        __nv_bfloat16 l0 = __float2bfloat16(v0 - __bfloat162float(h0));
                        __nv_bfloat16 l1 = __float2bfloat16(v1 - __bfloat162float(h1));
                        *(__nv_bfloat162*)(Chi + o) = bpack(h0, h1);
                        *(__nv_bfloat162*)(Clo + o) = bpack(l0, l1);
                    }
                }
            }
        }
    }
}

// ---------------- final linear [RTOT,512] -> o1/o2 [N,2] ---------------------
__global__ __launch_bounds__(256) void lin_kernel(const float* __restrict__ lw,
                                                  const float* __restrict__ lb)
{
    int gw   = (blockIdx.x * blockDim.x + threadIdx.x) >> 5;
    int lane = threadIdx.x & 31;
    if (gw >= RTOT) return;
    const float* __restrict__ row = g_x + (size_t)gw * HDIM;
    float a0 = 0.f, a1 = 0.f;
#pragma unroll 4
    for (int k = lane; k < HDIM; k += 32) {
        float v = row[k];
        a0 += v * lw[2 * k];
        a1 += v * lw[2 * k + 1];
    }
#pragma unroll
    for (int off = 16; off; off >>= 1) {
        a0 += __shfl_down_sync(0xffffffffu, a0, off);
        a1 += __shfl_down_sync(0xffffffffu, a1, off);
    }
    if (lane == 0) {
        float* o = (gw < N_NODES) ? g_o1 : g_o2;
        int n = (gw < N_NODES) ? gw : gw - N_NODES;
        o[n * 2 + 0] = a0 + lb[0];
        o[n * 2 + 1] = a1 + lb[1];
    }
}

// ---------------- pairwise distance ------------------------------------------
__global__ __launch_bounds__(256) void dist_kernel() {
    int i = blockIdx.x * blockDim.x + threadIdx.x;
    if (i < N_NODES) {
        float d0 = g_o1[2 * i]     - g_o2[2 * i]     + 1e-6f;
        float d1 = g_o1[2 * i + 1] - g_o2[2 * i + 1] + 1e-6f;
        g_dist[i] = sqrtf(d0 * d0 + d1 * d1);
    }
}

// ---------------- histogram-select top-k + MLP head, single block ------------
// dist >= 0 -> float bits are monotonic. 8192-bin histogram on bits>>19,
// suffix-scan for threshold bin, compact survivors, small bitonic sort.
#define HT 512
#define NBINS 8192
#define CCAP 8192
// dynamic smem offsets (bytes)
#define HS_BINS 0
#define HS_C    (NBINS * 4)
#define HS_PART (HS_C + CCAP * 4)
#define HS_RED  (HS_PART + HT * 4)
#define HS_H1   (HS_RED + HT * 4)
#define HS_H2   (HS_H1 + 128 * 4)
#define HS_MISC (HS_H2 + 512 * 4)
#define HEAD_SMEM (HS_MISC + 64)

__global__ __launch_bounds__(HT, 1)
void head_kernel(const float* __restrict__ fc1w, const float* __restrict__ fc1b,
                 const float* __restrict__ ln1g, const float* __restrict__ ln1b,
                 const float* __restrict__ fc2w, const float* __restrict__ fc2b,
                 const float* __restrict__ ln2g, const float* __restrict__ ln2b,
                 const float* __restrict__ fc3w, const float* __restrict__ fc3b,
                 float* __restrict__ out)
{
    extern __shared__ char hsm[];
    int*   bins    = (int*)(hsm + HS_BINS);
    float* C       = (float*)(hsm + HS_C);
    int*   partial = (int*)(hsm + HS_PART);
    float* red     = (float*)(hsm + HS_RED);
    float* h1      = (float*)(hsm + HS_H1);
    float* h2      = (float*)(hsm + HS_H2);
    float* misc    = (float*)(hsm + HS_MISC);
    int*   imisc   = (int*)(hsm + HS_MISC + 16);

    int tid = threadIdx.x;

    // 1. histogram
    for (int i = tid; i < NBINS; i += HT) bins[i] = 0;
    if (tid == 0) imisc[2] = 0;
    __syncthreads();
    for (int i = tid; i < N_NODES; i += HT) {
        uint32_t b = __float_as_uint(g_dist[i]) >> 19;
        atomicAdd(&bins[b], 1);
    }
    __syncthreads();

    // 2. per-thread chunk sums (16 bins each) + suffix scan
    {
        int base = tid * 16, loc = 0;
#pragma unroll
        for (int i = 0; i < 16; i++) loc += bins[base + i];
        partial[tid] = loc;
    }
    __syncthreads();
    for (int off = 1; off < HT; off <<= 1) {
        int v = (tid + off < HT) ? partial[tid + off] : 0;
        __syncthreads();
        partial[tid] += v;
        __syncthreads();
    }
    // partial[t] = count of values with bin >= t*16
    {
        int accNext = (tid < HT - 1) ? partial[tid + 1] : 0;
        int acc = accNext;                       // count with bin > current b
        for (int b = tid * 16 + 15; b >= tid * 16; b--) {
            int cb = bins[b];
            int ge = acc + cb;
            if (ge >= KTOP && acc < KTOP) { imisc[0] = b; }
            acc = ge;
        }
    }
    __syncthreads();
    int T = imisc[0];

    // 3. compact all values with bin >= T
    for (int i = tid; i < N_NODES; i += HT) {
        float v = g_dist[i];
        if ((int)(__float_as_uint(v) >> 19) >= T) {
            int p = atomicAdd(&imisc[2], 1);
            if (p < CCAP) C[p] = v;
        }
    }
    __syncthreads();
    int M = imisc[2];
    if (M > CCAP) M = CCAP;
    int P = 1024;
    while (P < M) P <<= 1;
    for (int i = M + tid; i < P; i += HT) C[i] = -1e30f;
    __syncthreads();

    // 4. ascending bitonic sort of P elems; top-k read reversed
    for (int k = 2; k <= P; k <<= 1) {
        for (int j = k >> 1; j > 0; j >>= 1) {
            for (int i = tid; i < P; i += HT) {
                int ixj = i ^ j;
                if (ixj > i) {
                    float a = C[i], b = C[ixj];
                    bool up = ((i & k) == 0);
                    if (up ? (a > b) : (a < b)) { C[i] = b; C[ixj] = a; }
                }
            }
            __syncthreads();
        }
    }
    // vals[r] = C[P-1-r]

    // 5. fc1 (K=1000 -> 128)
    {
        int part = tid >> 7;   // 0..3
        int j    = tid & 127;
        float acc = 0.f;
        for (int r = part; r < KTOP; r += 4)
            acc += C[P - 1 - r] * fc1w[r * 128 + j];
        red[part * 128 + j] = acc;
    }
    __syncthreads();
    if (tid < 128) {
        float v = fc1b[tid];
        for (int p = 0; p < 4; p++) v += red[p * 128 + tid];
        h1[tid] = v;
    }
    __syncthreads();
    if (tid == 0) {
        float m = 0.f;
        for (int i = 0; i < 128; i++) m += h1[i];
        m /= 128.f;
        float v = 0.f;
        for (int i = 0; i < 128; i++) { float d = h1[i] - m; v += d * d; }
        v /= 128.f;
        misc[0] = m;
        misc[1] = rsqrtf(v + 1e-5f);
    }
    __syncthreads();
    if (tid < 128) {
        float v = (h1[tid] - misc[0]) * misc[1] * ln1g[tid] + ln1b[tid];
        h1[tid] = fmaxf(v, 0.f);
    }
    __syncthreads();

    // fc2: 128 -> 512
    {
        float acc = fc2b[tid];
        for (int k = 0; k < 128; k++) acc += h1[k] * fc2w[k * 512 + tid];
        h2[tid] = acc;
    }
    __syncthreads();
    if (tid == 0) {
        float m = 0.f;
        for (int i = 0; i < 512; i++) m += h2[i];
        m /= 512.f;
        float v = 0.f;
        for (int i = 0; i < 512; i++) { float d = h2[i] - m; v += d * d; }
        v /= 512.f;
        misc[0] = m;
        misc[1] = rsqrtf(v + 1e-5f);
    }
    __syncthreads();
    {
        float v = (h2[tid] - misc[0]) * misc[1] * ln2g[tid] + ln2b[tid];
        red[tid] = fmaxf(v, 0.f) * fc3w[tid];
    }
    __syncthreads();
    if (tid == 0) {
        float z = fc3b[0];
        for (int i = 0; i < 512; i++) z += red[i];
        out[0] = 1.f / (1.f + expf(-z));
    }
}

// ---------------- launcher ---------------------------------------------------
extern "C" void kernel_launch(void* const* d_in, const int* in_sizes, int n_in,
                              void* d_out, int out_size)
{
    (void)in_sizes; (void)n_in; (void)out_size;
    const float* x1   = (const float*)d_in[0];
    const int*   ei1  = (const int*)  d_in[1];
    const float* x2   = (const float*)d_in[2];
    const int*   ei2  = (const int*)  d_in[3];
    const float* w11  = (const float*)d_in[4];
    const float* b11  = (const float*)d_in[5];
    const float* b12  = (const float*)d_in[7];
    const float* b21  = (const float*)d_in[9];
    const float* b22  = (const float*)d_in[11];
    const float* b31  = (const float*)d_in[13];
    const float* b32  = (const float*)d_in[15];
    const float* linw = (const float*)d_in[16];
    const float* linb = (const float*)d_in[17];
    const float* fc1w = (const float*)d_in[18];
    const float* fc1b = (const float*)d_in[19];
    const float* ln1g = (const float*)d_in[20];
    const float* ln1b = (const float*)d_in[21];
    const float* fc2w = (const float*)d_in[22];
    const float* fc2b = (const float*)d_in[23];
    const float* ln2g = (const float*)d_in[24];
    const float* ln2b = (const float*)d_in[25];
    const float* fc3w = (const float*)d_in[26];
    const float* fc3b = (const float*)d_in[27];
    float* out = (float*)d_out;

    float *p_x;
    __nv_bfloat16 *p_ahi, *p_alo, *p_thi, *p_tlo, *p_whi, *p_wlo;
    cudaGetSymbolAddress((void**)&p_x,   g_x);
    cudaGetSymbolAddress((void**)&p_ahi, g_ahi);
    cudaGetSymbolAddress((void**)&p_alo, g_alo);
    cudaGetSymbolAddress((void**)&p_thi, g_thi);
    cudaGetSymbolAddress((void**)&p_tlo, g_tlo);
    cudaGetSymbolAddress((void**)&p_whi, g_whi);
    cudaGetSymbolAddress((void**)&p_wlo, g_wlo);

    const size_t O11 = 0;
    const size_t O12 = 512 * 256;
    const size_t O21 = O12 + 512 * 512;
    const size_t O22 = O21 + 512 * 512;
    const size_t O31 = O22 + 512 * 512;
    const size_t O32 = O31 + 512 * 512;

    // weight prep
    wprep_kernel<<<(512 * 256 + 255) / 256, 256>>>(w11, 256, 512, p_whi + O11, p_wlo + O11);
    {
        dim3 wg((512 * 512 + 255) / 256, 1, 5);
        wprep5_kernel<<<wg, 256>>>((const float*)d_in[6], (const float*)d_in[8],
                                   (const float*)d_in[10], (const float*)d_in[12],
                                   (const float*)d_in[14], p_whi, p_wlo);
    }

    // CSR build (both graphs)
    zero_deg_kernel<<<(2 * N_NODES + 255) / 256, 256>>>();
    hist_kernel<<<(2 * N_EDGES + 255) / 256, 256>>>(ei1, ei2);
    scan_kernel<<<2, 256>>>();
    fill_kernel<<<(2 * N_EDGES + 255) / 256, 256>>>(ei1, ei2);

    cudaFuncSetAttribute(mma_gemm_kernel, cudaFuncAttributeMaxDynamicSharedMemorySize, GEMM_SMEM);
    dim3 ggrid((RTOT + 127) / 128, MOUT / 64);

    // layer 1 (K=256)
    agg256_kernel<<<RTOT, 128>>>(x1, x2);
    mma_gemm_kernel<<<ggrid, 256, GEMM_SMEM>>>(p_ahi, p_alo, p_whi + O11, p_wlo + O11, b11,
                                               nullptr, p_thi, p_tlo, 256, 1);
    mma_gemm_kernel<<<ggrid, 256, GEMM_SMEM>>>(p_thi, p_tlo, p_whi + O12, p_wlo + O12, b12,
                                               p_x, nullptr, nullptr, 512, 0);
    // layer 2
    agg512_kernel<<<RTOT, 128>>>();
    mma_gemm_kernel<<<ggrid, 256, GEMM_SMEM>>>(p_ahi, p_alo, p_whi + O21, p_wlo + O21, b21,
                                               nullptr, p_thi, p_tlo, 512, 1);
    mma_gemm_kernel<<<ggrid, 256, GEMM_SMEM>>>(p_thi, p_tlo, p_whi + O22, p_wlo + O22, b22,
                                               p_x, nullptr, nullptr, 512, 0);
    // layer 3
    agg512_kernel<<<RTOT, 128>>>();
    mma_gemm_kernel<<<ggrid, 256, GEMM_SMEM>>>(p_ahi, p_alo, p_whi + O31, p_wlo + O31, b31,
                                               nullptr, p_thi, p_tlo, 512, 1);
    mma_gemm_kernel<<<ggrid, 256, GEMM_SMEM>>>(p_thi, p_tlo, p_whi + O32, p_wlo + O32, b32,
                                               p_x, nullptr, nullptr, 512, 0);

    lin_kernel<<<(RTOT * 32 + 255) / 256, 256>>>(linw, linb);
    dist_kernel<<<(N_NODES + 255) / 256, 256>>>();

    cudaFuncSetAttribute(head_kernel, cudaFuncAttributeMaxDynamicSharedMemorySize, HEAD_SMEM);
    head_kernel<<<1, HT, HEAD_SMEM>>>(fc1w, fc1b, ln1g, ln1b,
                                      fc2w, fc2b, ln2g, ln2b,
                                      fc3w, fc3b, out);
}